// round 12
// baseline (speedup 1.0000x reference)
#include <cuda_runtime.h>
#include <cstdint>
#include <math.h>

#define T_STEPS 100
#define NPIX    784
#define NQUAD   196          /* 4-pixel groups */
#define NOUT    10
#define QSTR    162          /* LUT words per quad: 16 patterns * 10 + 2 pad */
#define WARPS_PB 28
#define THREADS  (WARPS_PB * 32)
#define NBATCH   16384

// Integer add forced onto the FMA pipe (IMAD): d = a*one + b, one==1 at runtime
// but opaque to the compiler so it cannot strength-reduce to IADD3.
__device__ __forceinline__ uint32_t madd(uint32_t a, uint32_t b, uint32_t one) {
    uint32_t d;
    asm("mad.lo.u32 %0, %1, %2, %3;" : "=r"(d) : "r"(a), "r"(one), "r"(b));
    return d;
}

struct TFK { uint32_t k0, k1, k2, i1, i2, i3, i4, i5; };

// JAX threefry2x32, exact; x0 initial = 0; injection consts precomputed per t.
__device__ __forceinline__ uint2 tf2x32(const TFK& K, uint32_t ctr, uint32_t one) {
    uint32_t x0 = K.k0;
    uint32_t x1 = madd(ctr, K.k1, one);
#define R(r) { x0 = madd(x0, x1, one); x1 = __funnelshift_l(x1, x1, (r)); x1 ^= x0; }
    R(13) R(15) R(26) R(6)
    x0 = madd(x0, K.k1, one); x1 = madd(x1, K.i1, one);
    R(17) R(29) R(16) R(24)
    x0 = madd(x0, K.k2, one); x1 = madd(x1, K.i2, one);
    R(13) R(15) R(26) R(6)
    x0 = madd(x0, K.k0, one); x1 = madd(x1, K.i3, one);
    R(17) R(29) R(16) R(24)
    x0 = madd(x0, K.k1, one); x1 = madd(x1, K.i4, one);
    R(13) R(15) R(26) R(6)
    x0 = madd(x0, K.k2, one); x1 = madd(x1, K.i5, one);
#undef R
    return make_uint2(x0, x1);
}

__device__ __forceinline__ uint32_t smem_u32(const void* p) {
    uint32_t a;
    asm("{ .reg .u64 t; cvta.to.shared.u64 t, %1; cvt.u32.u64 %0, t; }"
        : "=r"(a) : "l"(p));
    return a;
}

// smem: keys (800B) | quad-LUT (196*162*4 = 127008B) | xth (28*784*4 = 87808B)
//       | 512B guard pad (deepest threshold prefetch of warp 27 over-reads 464B)
#define SM_KEYS  0
#define SM_LUT   800
#define SM_XTH   (SM_LUT + NQUAD * QSTR * 4)
#define SM_TOTAL (SM_XTH + WARPS_PB * NPIX * 4 + 512)

__global__ void __launch_bounds__(THREADS, 1)
snn_kernel(const float* __restrict__ x, const float* __restrict__ W,
           float* __restrict__ out) {
    extern __shared__ unsigned char sm[];
    uint2*    keys = (uint2*)(sm + SM_KEYS);
    float*    LUT  = (float*)(sm + SM_LUT);
    uint32_t* xth  = (uint32_t*)(sm + SM_XTH);

    const int tid  = threadIdx.x;
    const int warp = tid >> 5;
    const int lane = tid & 31;
    const int b    = blockIdx.x * WARPS_PB + warp;
    const bool active = (b < NBATCH);
    const uint32_t base = active ? (uint32_t)b * NPIX : 0u;
    const uint32_t one  = (base >> 24) | 1u;     // == 1, opaque to compiler

    // --- per-timestep keys: split(key(42),100) partitionable/foldlike ---
    if (tid < T_STEPS) {
        TFK K0;
        K0.k0 = 0u; K0.k1 = 42u; K0.k2 = 0u ^ 42u ^ 0x1BD11BDAu;
        K0.i1 = K0.k2 + 1u; K0.i2 = K0.k0 + 2u; K0.i3 = K0.k1 + 3u;
        K0.i4 = K0.k2 + 4u; K0.i5 = K0.k0 + 5u;
        keys[tid] = tf2x32(K0, (uint32_t)tid, one);
    }

    // --- quad subset-sum LUT: LUT[g*162 + m*10 + o] = sum_{i in m} W[o][4g+i] ---
    for (int i = tid; i < NQUAD * 16 * NOUT; i += THREADS) {
        int g = i / 160;
        int r = i - g * 160;
        int m = r / 10, o = r - m * 10;
        const float* wrow = W + o * NPIX + 4 * g;
        float s = 0.0f;
        if (m & 1) s += wrow[0];
        if (m & 2) s += wrow[1];
        if (m & 4) s += wrow[2];
        if (m & 8) s += wrow[3];
        LUT[g * QSTR + m * 10 + o] = s;
    }

    // --- pre-shifted saturated thresholds:
    //     spike <=> (bits>>9) < t  <=>  bits < (t<<9), sat at t = 2^23 ---
    if (active) {
        uint32_t* th = xth + warp * NPIX;
        for (int p = lane; p < NPIX; p += 32) {
            double d = (double)x[(size_t)b * NPIX + p] * 8388608.0;
            uint32_t t = (uint32_t)ceil(d);
            th[p] = (t >= 8388608u) ? 0xFFFFFFFFu : (t << 9);
        }
    }
    __syncthreads();
    if (!active) return;

    const uint32_t th_s0  = smem_u32(xth + warp * NPIX) + (uint32_t)lane * 16u;
    const uint32_t lut_l0 = smem_u32(LUT) + (uint32_t)lane * (QSTR * 4);

    float v[NOUT], cnt[NOUT];
#pragma unroll
    for (int o = 0; o < NOUT; o++) { v[o] = 0.f; cnt[o] = 0.f; }

    for (int t = 0; t < T_STEPS; t++) {
        const uint2 kk = keys[t];
        TFK K;
        K.k0 = kk.x; K.k1 = kk.y; K.k2 = K.k0 ^ K.k1 ^ 0x1BD11BDAu;
        K.i1 = K.k2 + 1u; K.i2 = K.k0 + 2u; K.i3 = K.k1 + 3u;
        K.i4 = K.k2 + 4u; K.i5 = K.k0 + 5u;

        unsigned long long acc2[5];
#pragma unroll
        for (int k = 0; k < 5; k++) acc2[k] = 0ULL;

        // one quad (4 consecutive pixels) per lane per iter: h = lane + 32j
        uint32_t cA     = base + 4u * (uint32_t)lane;
        uint32_t th_ptr = th_s0;
        uint32_t lut_g  = lut_l0;

        uint4 th;
        asm("ld.shared.v4.u32 {%0,%1,%2,%3}, [%4];"
            : "=r"(th.x), "=r"(th.y), "=r"(th.z), "=r"(th.w) : "r"(th_ptr));

        // 196 quads = 6 iters * 32 + tail of 4 (lanes 0-3)
#pragma unroll 1
        for (int j = 0; j < 6; j++) {
            // 4 independent hash chains (consecutive counters)
            uint2 rA = tf2x32(K, cA,      one);
            uint2 rB = tf2x32(K, cA + 1u, one);
            uint2 rC = tf2x32(K, cA + 2u, one);
            uint2 rD = tf2x32(K, cA + 3u, one);

            // prefetch next iteration's thresholds (j=5 fetch feeds the tail:
            // its address is exactly the tail quad's thresholds for lanes 0-3)
            uint4 tn;
            asm("ld.shared.v4.u32 {%0,%1,%2,%3}, [%4+512];"
                : "=r"(tn.x), "=r"(tn.y), "=r"(tn.z), "=r"(tn.w) : "r"(th_ptr));

            uint32_t lp = lut_g
                        + (((rA.x ^ rA.y) < th.x) ? 40u : 0u)
                        + (((rB.x ^ rB.y) < th.y) ? 80u : 0u)
                        + (((rC.x ^ rC.y) < th.z) ? 160u : 0u)
                        + (((rD.x ^ rD.y) < th.w) ? 320u : 0u);
#pragma unroll
            for (int k = 0; k < 5; k++) {
                unsigned long long w;
                asm("ld.shared.b64 %0, [%1];" : "=l"(w) : "r"(lp + 8u * k));
                asm("add.rn.f32x2 %0, %1, %2;" : "=l"(acc2[k]) : "l"(acc2[k]), "l"(w));
            }

            th = tn;
            cA     = madd(cA, 128u, one);
            th_ptr = madd(th_ptr, 512u, one);
            lut_g  = madd(lut_g, 32u * QSTR * 4u, one);
        }
        if (lane < 4) {   // tail: quad h = 192 + lane; thresholds already in th
            uint2 rA = tf2x32(K, cA,      one);
            uint2 rB = tf2x32(K, cA + 1u, one);
            uint2 rC = tf2x32(K, cA + 2u, one);
            uint2 rD = tf2x32(K, cA + 3u, one);
            uint32_t lp = lut_g
                        + (((rA.x ^ rA.y) < th.x) ? 40u : 0u)
                        + (((rB.x ^ rB.y) < th.y) ? 80u : 0u)
                        + (((rC.x ^ rC.y) < th.z) ? 160u : 0u)
                        + (((rD.x ^ rD.y) < th.w) ? 320u : 0u);
#pragma unroll
            for (int k = 0; k < 5; k++) {
                unsigned long long w;
                asm("ld.shared.b64 %0, [%1];" : "=l"(w) : "r"(lp + 8u * k));
                asm("add.rn.f32x2 %0, %1, %2;" : "=l"(acc2[k]) : "l"(acc2[k]), "l"(w));
            }
        }

        // unpack (reg-pair alias, free) and scalar butterfly reduce
        float acc[NOUT];
#pragma unroll
        for (int k = 0; k < 5; k++)
            asm("mov.b64 {%0, %1}, %2;" : "=f"(acc[2 * k]), "=f"(acc[2 * k + 1]) : "l"(acc2[k]));
#pragma unroll
        for (int off = 16; off > 0; off >>= 1) {
#pragma unroll
            for (int o = 0; o < NOUT; o++)
                acc[o] += __shfl_xor_sync(0xFFFFFFFFu, acc[o], off);
        }

        // LIF: v += (I - v)/2 ; spike if v>=1 ; hard reset (bit-exact vs XLA)
#pragma unroll
        for (int o = 0; o < NOUT; o++) {
            float nv = fmaf(acc[o] - v[o], 0.5f, v[o]);
            if (nv >= 1.0f) { cnt[o] += 1.0f; nv = 0.0f; }
            v[o] = nv;
        }
    }

    if (lane == 0) {
#pragma unroll
        for (int o = 0; o < NOUT; o++)
            out[(size_t)b * NOUT + o] = cnt[o] / 100.0f;
    }
}

extern "C" void kernel_launch(void* const* d_in, const int* in_sizes, int n_in,
                              void* d_out, int out_size) {
    const float* x = (const float*)d_in[0];   // [16384,1,28,28] f32
    const float* W = (const float*)d_in[1];   // [10,784] f32
    float* out = (float*)d_out;               // [16384,10] f32

    const int nblocks = (NBATCH + WARPS_PB - 1) / WARPS_PB;   // 586
    cudaFuncSetAttribute(snn_kernel, cudaFuncAttributeMaxDynamicSharedMemorySize,
                         SM_TOTAL);
    snn_kernel<<<nblocks, THREADS, SM_TOTAL>>>(x, W, out);
}

// round 13
// speedup vs baseline: 1.0884x; 1.0884x over previous
#include <cuda_runtime.h>
#include <cstdint>
#include <math.h>

#define T_STEPS 100
#define NPIX    784
#define NPAIR   392
#define NOUT    10
#define LSTR    42           /* LUT stride words: 4*10 + 2 pad; 8B-aligned */
#define WARPS_PB 28
#define THREADS  (WARPS_PB * 32)
#define NBATCH   16384

// Integer add forced onto the FMA pipe (IMAD): d = a*one + b, one==1 at runtime
// but opaque to the compiler so it cannot strength-reduce to IADD3.
__device__ __forceinline__ uint32_t madd(uint32_t a, uint32_t b, uint32_t one) {
    uint32_t d;
    asm("mad.lo.u32 %0, %1, %2, %3;" : "=r"(d) : "r"(a), "r"(one), "r"(b));
    return d;
}

struct TFK { uint32_t k0, k1, k2, i1, i2, i3, i4, i5; };

// JAX threefry2x32, exact; x0 initial = 0; injection consts precomputed per t.
__device__ __forceinline__ uint2 tf2x32(const TFK& K, uint32_t ctr, uint32_t one) {
    uint32_t x0 = K.k0;
    uint32_t x1 = madd(ctr, K.k1, one);
#define R(r) { x0 = madd(x0, x1, one); x1 = __funnelshift_l(x1, x1, (r)); x1 ^= x0; }
    R(13) R(15) R(26) R(6)
    x0 = madd(x0, K.k1, one); x1 = madd(x1, K.i1, one);
    R(17) R(29) R(16) R(24)
    x0 = madd(x0, K.k2, one); x1 = madd(x1, K.i2, one);
    R(13) R(15) R(26) R(6)
    x0 = madd(x0, K.k0, one); x1 = madd(x1, K.i3, one);
    R(17) R(29) R(16) R(24)
    x0 = madd(x0, K.k1, one); x1 = madd(x1, K.i4, one);
    R(13) R(15) R(26) R(6)
    x0 = madd(x0, K.k2, one); x1 = madd(x1, K.i5, one);
#undef R
    return make_uint2(x0, x1);
}

__device__ __forceinline__ uint32_t smem_u32(const void* p) {
    uint32_t a;
    asm("{ .reg .u64 t; cvta.to.shared.u64 t, %1; cvt.u32.u64 %0, t; }"
        : "=r"(a) : "l"(p));
    return a;
}

// smem: keys (800B) | pair-LUT (392*42*4 = 65856B) | xth (28*784*4 = 87808B)
//       | 512B guard pad for the deepest threshold prefetch of the last warp
#define SM_KEYS  0
#define SM_LUT   800
#define SM_XTH   (SM_LUT + NPAIR * LSTR * 4)
#define SM_TOTAL (SM_XTH + WARPS_PB * NPIX * 4 + 512)

__global__ void __launch_bounds__(THREADS, 1)
snn_kernel(const float* __restrict__ x, const float* __restrict__ W,
           float* __restrict__ out) {
    extern __shared__ unsigned char sm[];
    uint2*    keys = (uint2*)(sm + SM_KEYS);
    float*    LUT  = (float*)(sm + SM_LUT);
    uint32_t* xth  = (uint32_t*)(sm + SM_XTH);

    const int tid  = threadIdx.x;
    const int warp = tid >> 5;
    const int lane = tid & 31;
    const int b    = blockIdx.x * WARPS_PB + warp;
    const bool active = (b < NBATCH);
    const uint32_t base = active ? (uint32_t)b * NPIX : 0u;
    const uint32_t one  = (base >> 24) | 1u;     // == 1, opaque to compiler

    // --- per-timestep keys: split(key(42),100) partitionable/foldlike ---
    if (tid < T_STEPS) {
        TFK K0;
        K0.k0 = 0u; K0.k1 = 42u; K0.k2 = 0u ^ 42u ^ 0x1BD11BDAu;
        K0.i1 = K0.k2 + 1u; K0.i2 = K0.k0 + 2u; K0.i3 = K0.k1 + 3u;
        K0.i4 = K0.k2 + 4u; K0.i5 = K0.k0 + 5u;
        keys[tid] = tf2x32(K0, (uint32_t)tid, one);
    }

    // --- pair subset-sum LUT: LUT[g*42 + m*10 + o] ---
    for (int i = tid; i < NPAIR * 4 * NOUT; i += THREADS) {
        int g = i / 40;
        int r = i - g * 40;
        int m = r / 10, o = r - m * 10;
        float s = 0.0f;
        if (m & 1) s += W[o * NPIX + 2 * g];
        if (m & 2) s += W[o * NPIX + 2 * g + 1];
        LUT[g * LSTR + m * 10 + o] = s;
    }

    // --- pre-shifted saturated thresholds:
    //     spike <=> (bits>>9) < t  <=>  bits < (t<<9), sat at t = 2^23 ---
    if (active) {
        uint32_t* th = xth + warp * NPIX;
        for (int p = lane; p < NPIX; p += 32) {
            double d = (double)x[(size_t)b * NPIX + p] * 8388608.0;
            uint32_t t = (uint32_t)ceil(d);
            th[p] = (t >= 8388608u) ? 0xFFFFFFFFu : (t << 9);
        }
    }
    __syncthreads();
    if (!active) return;

    const uint32_t th_s0  = smem_u32(xth + warp * NPIX) + (uint32_t)lane * 8u;
    const uint32_t lut_l0 = smem_u32(LUT) + (uint32_t)lane * (LSTR * 4);

    float v[NOUT], cnt[NOUT];
#pragma unroll
    for (int o = 0; o < NOUT; o++) { v[o] = 0.f; cnt[o] = 0.f; }

    for (int t = 0; t < T_STEPS; t++) {
        const uint2 kk = keys[t];
        TFK K;
        K.k0 = kk.x; K.k1 = kk.y; K.k2 = K.k0 ^ K.k1 ^ 0x1BD11BDAu;
        K.i1 = K.k2 + 1u; K.i2 = K.k0 + 2u; K.i3 = K.k1 + 3u;
        K.i4 = K.k2 + 4u; K.i5 = K.k0 + 5u;

        unsigned long long acc2[5];
#pragma unroll
        for (int k = 0; k < 5; k++) acc2[k] = 0ULL;

        // 2 pairs per lane per iter: g = lane + 64j and g + 32
        uint32_t cA     = base + 2u * (uint32_t)lane;
        uint32_t th_ptr = th_s0;
        uint32_t lut_g  = lut_l0;

        uint2 thA, thB;
        asm("ld.shared.v2.u32 {%0,%1}, [%2];"     : "=r"(thA.x), "=r"(thA.y) : "r"(th_ptr));
        asm("ld.shared.v2.u32 {%0,%1}, [%2+256];" : "=r"(thB.x), "=r"(thB.y) : "r"(th_ptr));

        // 392 pairs = 6 iters * 64 pairs + tail of 8 (lanes 0-7)
#pragma unroll 2
        for (int j = 0; j < 6; j++) {
            // 4 independent hash chains -> high per-warp ILP
            uint2 rA = tf2x32(K, cA,       one);
            uint2 rB = tf2x32(K, cA + 1u,  one);
            uint2 rC = tf2x32(K, cA + 64u, one);
            uint2 rD = tf2x32(K, cA + 65u, one);

            // prefetch next iteration's thresholds (j=5 fetch feeds the tail)
            uint2 tA, tB;
            asm("ld.shared.v2.u32 {%0,%1}, [%2+512];" : "=r"(tA.x), "=r"(tA.y) : "r"(th_ptr));
            asm("ld.shared.v2.u32 {%0,%1}, [%2+768];" : "=r"(tB.x), "=r"(tB.y) : "r"(th_ptr));

            uint32_t mA = (((rA.x ^ rA.y) < thA.x) ? 40u : 0u)
                        | (((rB.x ^ rB.y) < thA.y) ? 80u : 0u);
            uint32_t mB = (((rC.x ^ rC.y) < thB.x) ? 40u : 0u)
                        | (((rD.x ^ rD.y) < thB.y) ? 80u : 0u);
            uint32_t lpA = madd(mA, lut_g, one);             // pair A LUT row
            uint32_t lpB = madd(mB, lut_g, one);             // pair B row base (-ofs)
#pragma unroll
            for (int k = 0; k < 5; k++) {
                unsigned long long wA, wB;
                asm("ld.shared.b64 %0, [%1];" : "=l"(wA) : "r"(lpA + 8u * k));
                asm("add.rn.f32x2 %0, %1, %2;" : "=l"(acc2[k]) : "l"(acc2[k]), "l"(wA));
                asm("ld.shared.b64 %0, [%1+5376];" : "=l"(wB) : "r"(lpB + 8u * k)); // +32*42*4
                asm("add.rn.f32x2 %0, %1, %2;" : "=l"(acc2[k]) : "l"(acc2[k]), "l"(wB));
            }

            thA = tA; thB = tB;
            cA     = madd(cA, 128u, one);
            th_ptr = madd(th_ptr, 512u, one);
            lut_g  = madd(lut_g, 64u * LSTR * 4u, one);
        }
        if (lane < 8) {   // tail: pair g = 384 + lane, thresholds already in thA
            uint2 rA = tf2x32(K, cA,      one);
            uint2 rB = tf2x32(K, cA + 1u, one);
            uint32_t m = (((rA.x ^ rA.y) < thA.x) ? 40u : 0u)
                       | (((rB.x ^ rB.y) < thA.y) ? 80u : 0u);
            uint32_t lp = madd(m, lut_g, one);
#pragma unroll
            for (int k = 0; k < 5; k++) {
                unsigned long long w;
                asm("ld.shared.b64 %0, [%1];" : "=l"(w) : "r"(lp + 8u * k));
                asm("add.rn.f32x2 %0, %1, %2;" : "=l"(acc2[k]) : "l"(acc2[k]), "l"(w));
            }
        }

        // packed butterfly: accumulators stay f32x2; the mov.b64 splits are
        // register-pair aliases (free); 2 SHFL + 1 FADD2 per reg per step.
#pragma unroll
        for (int off = 16; off > 0; off >>= 1) {
#pragma unroll
            for (int k = 0; k < 5; k++) {
                uint32_t lo, hi;
                asm("mov.b64 {%0, %1}, %2;" : "=r"(lo), "=r"(hi) : "l"(acc2[k]));
                lo = __shfl_xor_sync(0xFFFFFFFFu, lo, off);
                hi = __shfl_xor_sync(0xFFFFFFFFu, hi, off);
                unsigned long long other;
                asm("mov.b64 %0, {%1, %2};" : "=l"(other) : "r"(lo), "r"(hi));
                asm("add.rn.f32x2 %0, %1, %2;" : "=l"(acc2[k]) : "l"(acc2[k]), "l"(other));
            }
        }

        float acc[NOUT];
#pragma unroll
        for (int k = 0; k < 5; k++)
            asm("mov.b64 {%0, %1}, %2;" : "=f"(acc[2 * k]), "=f"(acc[2 * k + 1]) : "l"(acc2[k]));

        // LIF: v += (I - v)/2 ; spike if v>=1 ; hard reset (bit-exact vs XLA)
#pragma unroll
        for (int o = 0; o < NOUT; o++) {
            float nv = fmaf(acc[o] - v[o], 0.5f, v[o]);
            if (nv >= 1.0f) { cnt[o] += 1.0f; nv = 0.0f; }
            v[o] = nv;
        }
    }

    if (lane == 0) {
#pragma unroll
        for (int o = 0; o < NOUT; o++)
            out[(size_t)b * NOUT + o] = cnt[o] / 100.0f;
    }
}

extern "C" void kernel_launch(void* const* d_in, const int* in_sizes, int n_in,
                              void* d_out, int out_size) {
    const float* x = (const float*)d_in[0];   // [16384,1,28,28] f32
    const float* W = (const float*)d_in[1];   // [10,784] f32
    float* out = (float*)d_out;               // [16384,10] f32

    const int nblocks = (NBATCH + WARPS_PB - 1) / WARPS_PB;   // 586
    cudaFuncSetAttribute(snn_kernel, cudaFuncAttributeMaxDynamicSharedMemorySize,
                         SM_TOTAL);
    snn_kernel<<<nblocks, THREADS, SM_TOTAL>>>(x, W, out);
}

// round 14
// speedup vs baseline: 1.1063x; 1.0165x over previous
#include <cuda_runtime.h>
#include <cstdint>
#include <math.h>

#define T_STEPS 100
#define NPIX    784
#define NPAIR   392
#define NOUT    10
#define LSTR    42           /* LUT stride words: 4*10 + 2 pad; 8B-aligned */
#define WARPS_PB 28
#define THREADS  (WARPS_PB * 32)
#define NBATCH   16384

// Integer add forced onto the FMA pipe (IMAD): d = a*one + b, one==1 at runtime
// but opaque to the compiler so it cannot strength-reduce to IADD3.
__device__ __forceinline__ uint32_t madd(uint32_t a, uint32_t b, uint32_t one) {
    uint32_t d;
    asm("mad.lo.u32 %0, %1, %2, %3;" : "=r"(d) : "r"(a), "r"(one), "r"(b));
    return d;
}

struct TFK { uint32_t k0, k1, k2, i1, i2, i3, i4, i5; };

// JAX threefry2x32, exact; x0 initial = 0; injection consts precomputed per t.
// k1x = K.k1 + counter_offset (hoisted per timestep), so the caller passes the
// base counter and the offset rides in the key: x1 = ctr + (k1 + delta).
__device__ __forceinline__ uint2 tf2x32(const TFK& K, uint32_t ctr, uint32_t k1x,
                                        uint32_t one) {
    uint32_t x0 = K.k0;
    uint32_t x1 = madd(ctr, k1x, one);
#define R(r) { x0 = madd(x0, x1, one); x1 = __funnelshift_l(x1, x1, (r)); x1 ^= x0; }
    R(13) R(15) R(26) R(6)
    x0 = madd(x0, K.k1, one); x1 = madd(x1, K.i1, one);
    R(17) R(29) R(16) R(24)
    x0 = madd(x0, K.k2, one); x1 = madd(x1, K.i2, one);
    R(13) R(15) R(26) R(6)
    x0 = madd(x0, K.k0, one); x1 = madd(x1, K.i3, one);
    R(17) R(29) R(16) R(24)
    x0 = madd(x0, K.k1, one); x1 = madd(x1, K.i4, one);
    R(13) R(15) R(26) R(6)
    x0 = madd(x0, K.k2, one); x1 = madd(x1, K.i5, one);
#undef R
    return make_uint2(x0, x1);
}

__device__ __forceinline__ uint32_t smem_u32(const void* p) {
    uint32_t a;
    asm("{ .reg .u64 t; cvta.to.shared.u64 t, %1; cvt.u32.u64 %0, t; }"
        : "=r"(a) : "l"(p));
    return a;
}

// mask = 0xFFFFFFFF if a < b else 0 (single SET op)
__device__ __forceinline__ uint32_t ltmask(uint32_t a, uint32_t b) {
    uint32_t m;
    asm("set.lt.u32.u32 %0, %1, %2;" : "=r"(m) : "r"(a), "r"(b));
    return m;
}

// lp = base + s0*(-40) + s1*(-80): two IMADs with immediate multipliers (fma pipe);
// s in {0, -1} so contributions are {0, +40} / {0, +80}.
__device__ __forceinline__ uint32_t lutaddr(uint32_t base, uint32_t s0, uint32_t s1) {
    uint32_t t, d;
    asm("mad.lo.u32 %0, %1, -40, %2;" : "=r"(t) : "r"(s0), "r"(base));
    asm("mad.lo.u32 %0, %1, -80, %2;" : "=r"(d) : "r"(s1), "r"(t));
    return d;
}

// smem: keys (800B) | pair-LUT (392*42*4 = 65856B) | xth (28*784*4 = 87808B)
//       | 512B guard pad for the deepest threshold prefetch of the last warp
#define SM_KEYS  0
#define SM_LUT   800
#define SM_XTH   (SM_LUT + NPAIR * LSTR * 4)
#define SM_TOTAL (SM_XTH + WARPS_PB * NPIX * 4 + 512)

__global__ void __launch_bounds__(THREADS, 1)
snn_kernel(const float* __restrict__ x, const float* __restrict__ W,
           float* __restrict__ out) {
    extern __shared__ unsigned char sm[];
    uint2*    keys = (uint2*)(sm + SM_KEYS);
    float*    LUT  = (float*)(sm + SM_LUT);
    uint32_t* xth  = (uint32_t*)(sm + SM_XTH);

    const int tid  = threadIdx.x;
    const int warp = tid >> 5;
    const int lane = tid & 31;
    const int b    = blockIdx.x * WARPS_PB + warp;
    const bool active = (b < NBATCH);
    const uint32_t base = active ? (uint32_t)b * NPIX : 0u;
    const uint32_t one  = (base >> 24) | 1u;     // == 1, opaque to compiler

    // --- per-timestep keys: split(key(42),100) partitionable/foldlike ---
    if (tid < T_STEPS) {
        TFK K0;
        K0.k0 = 0u; K0.k1 = 42u; K0.k2 = 0u ^ 42u ^ 0x1BD11BDAu;
        K0.i1 = K0.k2 + 1u; K0.i2 = K0.k0 + 2u; K0.i3 = K0.k1 + 3u;
        K0.i4 = K0.k2 + 4u; K0.i5 = K0.k0 + 5u;
        keys[tid] = tf2x32(K0, (uint32_t)tid, K0.k1, one);
    }

    // --- pair subset-sum LUT: LUT[g*42 + m*10 + o] ---
    for (int i = tid; i < NPAIR * 4 * NOUT; i += THREADS) {
        int g = i / 40;
        int r = i - g * 40;
        int m = r / 10, o = r - m * 10;
        float s = 0.0f;
        if (m & 1) s += W[o * NPIX + 2 * g];
        if (m & 2) s += W[o * NPIX + 2 * g + 1];
        LUT[g * LSTR + m * 10 + o] = s;
    }

    // --- pre-shifted saturated thresholds:
    //     spike <=> (bits>>9) < t  <=>  bits < (t<<9), sat at t = 2^23 ---
    if (active) {
        uint32_t* th = xth + warp * NPIX;
        for (int p = lane; p < NPIX; p += 32) {
            double d = (double)x[(size_t)b * NPIX + p] * 8388608.0;
            uint32_t t = (uint32_t)ceil(d);
            th[p] = (t >= 8388608u) ? 0xFFFFFFFFu : (t << 9);
        }
    }
    __syncthreads();
    if (!active) return;

    const uint32_t th_s0  = smem_u32(xth + warp * NPIX) + (uint32_t)lane * 8u;
    const uint32_t lut_l0 = smem_u32(LUT) + (uint32_t)lane * (LSTR * 4);

    float v[NOUT], cnt[NOUT];
#pragma unroll
    for (int o = 0; o < NOUT; o++) { v[o] = 0.f; cnt[o] = 0.f; }

    for (int t = 0; t < T_STEPS; t++) {
        const uint2 kk = keys[t];
        TFK K;
        K.k0 = kk.x; K.k1 = kk.y; K.k2 = K.k0 ^ K.k1 ^ 0x1BD11BDAu;
        K.i1 = K.k2 + 1u; K.i2 = K.k0 + 2u; K.i3 = K.k1 + 3u;
        K.i4 = K.k2 + 4u; K.i5 = K.k0 + 5u;
        // hoisted counter-offset keys: x1 = cA + (k1 + delta)
        const uint32_t k1p0  = K.k1;
        const uint32_t k1p1  = K.k1 + 1u;
        const uint32_t k1p64 = K.k1 + 64u;
        const uint32_t k1p65 = K.k1 + 65u;

        unsigned long long acc2[5];
#pragma unroll
        for (int k = 0; k < 5; k++) acc2[k] = 0ULL;

        // 2 pairs per lane per iter: g = lane + 64j and g + 32
        uint32_t cA     = base + 2u * (uint32_t)lane;
        uint32_t th_ptr = th_s0;
        uint32_t lut_g  = lut_l0;

        uint2 thA, thB;
        asm("ld.shared.v2.u32 {%0,%1}, [%2];"     : "=r"(thA.x), "=r"(thA.y) : "r"(th_ptr));
        asm("ld.shared.v2.u32 {%0,%1}, [%2+256];" : "=r"(thB.x), "=r"(thB.y) : "r"(th_ptr));

        // 392 pairs = 6 iters * 64 pairs + tail of 8 (lanes 0-7)
#pragma unroll 3
        for (int j = 0; j < 6; j++) {
            // 4 independent hash chains; counter offsets ride in the keys
            uint2 rA = tf2x32(K, cA, k1p0,  one);
            uint2 rB = tf2x32(K, cA, k1p1,  one);
            uint2 rC = tf2x32(K, cA, k1p64, one);
            uint2 rD = tf2x32(K, cA, k1p65, one);

            // prefetch next iteration's thresholds (j=5 fetch feeds the tail)
            uint2 tA, tB;
            asm("ld.shared.v2.u32 {%0,%1}, [%2+512];" : "=r"(tA.x), "=r"(tA.y) : "r"(th_ptr));
            asm("ld.shared.v2.u32 {%0,%1}, [%2+768];" : "=r"(tB.x), "=r"(tB.y) : "r"(th_ptr));

            uint32_t sA0 = ltmask(rA.x ^ rA.y, thA.x);
            uint32_t sA1 = ltmask(rB.x ^ rB.y, thA.y);
            uint32_t sB0 = ltmask(rC.x ^ rC.y, thB.x);
            uint32_t sB1 = ltmask(rD.x ^ rD.y, thB.y);
            uint32_t lpA = lutaddr(lut_g, sA0, sA1);         // pair A LUT row
            uint32_t lpB = lutaddr(lut_g, sB0, sB1);         // pair B row base (-ofs)
#pragma unroll
            for (int k = 0; k < 5; k++) {
                unsigned long long wA, wB;
                asm("ld.shared.b64 %0, [%1];" : "=l"(wA) : "r"(lpA + 8u * k));
                asm("add.rn.f32x2 %0, %1, %2;" : "=l"(acc2[k]) : "l"(acc2[k]), "l"(wA));
                asm("ld.shared.b64 %0, [%1+5376];" : "=l"(wB) : "r"(lpB + 8u * k)); // +32*42*4
                asm("add.rn.f32x2 %0, %1, %2;" : "=l"(acc2[k]) : "l"(acc2[k]), "l"(wB));
            }

            thA = tA; thB = tB;
            cA     = madd(cA, 128u, one);
            th_ptr = madd(th_ptr, 512u, one);
            lut_g  = madd(lut_g, 64u * LSTR * 4u, one);
        }
        if (lane < 8) {   // tail: pair g = 384 + lane, thresholds already in thA
            uint2 rA = tf2x32(K, cA, k1p0, one);
            uint2 rB = tf2x32(K, cA, k1p1, one);
            uint32_t s0 = ltmask(rA.x ^ rA.y, thA.x);
            uint32_t s1 = ltmask(rB.x ^ rB.y, thA.y);
            uint32_t lp = lutaddr(lut_g, s0, s1);
#pragma unroll
            for (int k = 0; k < 5; k++) {
                unsigned long long w;
                asm("ld.shared.b64 %0, [%1];" : "=l"(w) : "r"(lp + 8u * k));
                asm("add.rn.f32x2 %0, %1, %2;" : "=l"(acc2[k]) : "l"(acc2[k]), "l"(w));
            }
        }

        // packed butterfly: accumulators stay f32x2; the mov.b64 splits are
        // register-pair aliases (free); 2 SHFL + 1 FADD2 per reg per step.
#pragma unroll
        for (int off = 16; off > 0; off >>= 1) {
#pragma unroll
            for (int k = 0; k < 5; k++) {
                uint32_t lo, hi;
                asm("mov.b64 {%0, %1}, %2;" : "=r"(lo), "=r"(hi) : "l"(acc2[k]));
                lo = __shfl_xor_sync(0xFFFFFFFFu, lo, off);
                hi = __shfl_xor_sync(0xFFFFFFFFu, hi, off);
                unsigned long long other;
                asm("mov.b64 %0, {%1, %2};" : "=l"(other) : "r"(lo), "r"(hi));
                asm("add.rn.f32x2 %0, %1, %2;" : "=l"(acc2[k]) : "l"(acc2[k]), "l"(other));
            }
        }

        float acc[NOUT];
#pragma unroll
        for (int k = 0; k < 5; k++)
            asm("mov.b64 {%0, %1}, %2;" : "=f"(acc[2 * k]), "=f"(acc[2 * k + 1]) : "l"(acc2[k]));

        // LIF: v += (I - v)/2 ; spike if v>=1 ; hard reset (bit-exact vs XLA)
#pragma unroll
        for (int o = 0; o < NOUT; o++) {
            float nv = fmaf(acc[o] - v[o], 0.5f, v[o]);
            if (nv >= 1.0f) { cnt[o] += 1.0f; nv = 0.0f; }
            v[o] = nv;
        }
    }

    if (lane == 0) {
#pragma unroll
        for (int o = 0; o < NOUT; o++)
            out[(size_t)b * NOUT + o] = cnt[o] / 100.0f;
    }
}

extern "C" void kernel_launch(void* const* d_in, const int* in_sizes, int n_in,
                              void* d_out, int out_size) {
    const float* x = (const float*)d_in[0];   // [16384,1,28,28] f32
    const float* W = (const float*)d_in[1];   // [10,784] f32
    float* out = (float*)d_out;               // [16384,10] f32

    const int nblocks = (NBATCH + WARPS_PB - 1) / WARPS_PB;   // 586
    cudaFuncSetAttribute(snn_kernel, cudaFuncAttributeMaxDynamicSharedMemorySize,
                         SM_TOTAL);
    snn_kernel<<<nblocks, THREADS, SM_TOTAL>>>(x, W, out);
}